// round 4
// baseline (speedup 1.0000x reference)
#include <cuda_runtime.h>
#include <cuda_fp16.h>
#include <math.h>

// Problem constants
#define LS       32
#define SB       1024            // S = LS*LS
#define NB       16              // batch
#define NE       1024            // embedding
#define BE       (NB*NE)         // 16384: stride between spatial positions
#define S_TOT    (SB*NB*NE)      // 16,777,216 elements

// fp16 scratch for all 4 direction outputs (128 MB)
__device__ __half g_scrh[4][S_TOT];

typedef unsigned long long u64;

__device__ __forceinline__ float sigm(float v) { return 1.0f / (1.0f + expf(-v)); }

// ---- packed f32x2 helpers (sm_103a paired-fp32 ops, PTX-only) ----
__device__ __forceinline__ u64 pack2(float lo, float hi) {
    u64 r; asm("mov.b64 %0, {%1,%2};" : "=l"(r) : "f"(lo), "f"(hi)); return r;
}
__device__ __forceinline__ float2 unpack2(u64 v) {
    float2 r; asm("mov.b64 {%0,%1}, %2;" : "=f"(r.x), "=f"(r.y) : "l"(v)); return r;
}
__device__ __forceinline__ u64 fma2(u64 a, u64 b, u64 c) {
    u64 d; asm("fma.rn.f32x2 %0,%1,%2,%3;" : "=l"(d) : "l"(a), "l"(b), "l"(c)); return d;
}
__device__ __forceinline__ u64 mul2(u64 a, u64 b) {
    u64 d; asm("mul.rn.f32x2 %0,%1,%2;" : "=l"(d) : "l"(a), "l"(b)); return d;
}

__device__ __forceinline__ void st_h2_cs(__half* p, __half2 v) {
    unsigned raw = *reinterpret_cast<unsigned*>(&v);
    asm volatile("st.global.cs.u32 [%0], %1;" :: "l"(p), "r"(raw) : "memory");
}

// ---------------------------------------------------------------------------
// Scan kernel: one thread per (dir, b, e-pair). 2D SSM recurrence (= causal
// 2D conv with the impulse response) on the direction-flipped image, plus
// the two 1D boundary-correction recurrences implementing the reference's
// K row-0/col-0 doubling. N=2 packed in f32x2; 2 adjacent e per thread so
// input loads are LDG.64 and scratch stores are STG.32 (half2).
//
// Reparametrized states (11 f32x2/pixel):
//   p   = a3*xh            p' = a1*p + (a3a2)*xv + (a3b1)*u
//   nv  = z + b2*u         (z = smem carry from row above)
//   z'  = p' + a4*nv
//   ns' : ns'=a1*ns'+u_prev   (row-0 corr, scaled by w into cw1)
//   t'  : y uses old t', then t'=a4*t'+u (col-0 corr, scaled into cw2)
//   y   = (c1/a3).p' + (c1w).ns' + c2.nv + (c2w2).t'
//
// 4-row register blocking, 32-thread CTAs, 32KB smem -> 7 CTAs/SM, 1 wave.
// ---------------------------------------------------------------------------
__global__ void __launch_bounds__(32) ssm_scan(
    const float* __restrict__ x,
    const float* __restrict__ A1v, const float* __restrict__ A2v,
    const float* __restrict__ A3v, const float* __restrict__ A4v,
    const float* __restrict__ B1v, const float* __restrict__ B2v,
    const float* __restrict__ C1v, const float* __restrict__ C2v)
{
    __shared__ ulonglong2 sh_z[LS][32];   // per-(column, e-pair) vertical carry
    __shared__ ulonglong2 sh_t[LS][32];   // per-(column, e-pair) col-0 state

    const int tid = threadIdx.x;
    const int g   = blockIdx.x * 32 + tid;
    const int ep  = g & 511;                 // e-pair index: e0 = 2*ep
    const int b   = (g >> 9) & (NB - 1);
    const int dir = g >> 13;                 // 0..3
    const int e0  = ep * 2;
    const int h0  = (dir << 6) | (e0 & 63);  // kernel channel for e0 (h0+1 for e1)
    const bool fi = (dir & 1) != 0;          // flip rows (axis -2)
    const bool fj = (dir & 2) != 0;          // flip cols (axis -1)

    const float scale = 0.70710678118654752440f;  // sqrt(1/N), N=2

    u64 a1e[2], a32[2], a31[2], bb2e[2], a4e[2], c1p[2], c2e[2], cw1[2], cw2[2];
#pragma unroll
    for (int ee = 0; ee < 2; ee++) {
        const int h = h0 + ee;
        float p1[2], p2[2], p3[2], p4[2], q1[2], q2[2], r1[2], r2[2];
#pragma unroll
        for (int n = 0; n < 2; n++) {
            p1[n] = sigm(A1v[2 * h + n]);
            p2[n] = sigm(A2v[2 * h + n]);
            p3[n] = sigm(A3v[2 * h + n]);
            p4[n] = sigm(A4v[2 * h + n]);
            q1[n] = sigm(B1v[2 * h + n]);
            q2[n] = sigm(B2v[2 * h + n]);
            r1[n] = scale * C1v[2 * h + n];
            r2[n] = scale * C2v[2 * h + n];
        }
        a1e[ee]  = pack2(p1[0], p1[1]);
        a32[ee]  = pack2(p3[0] * p2[0], p3[1] * p2[1]);
        a31[ee]  = pack2(p3[0] * q1[0], p3[1] * q1[1]);
        bb2e[ee] = pack2(q2[0], q2[1]);
        a4e[ee]  = pack2(p4[0], p4[1]);
        c1p[ee]  = pack2(r1[0] / p3[0], r1[1] / p3[1]);
        c2e[ee]  = pack2(r2[0], r2[1]);
        // w = a1b1+a2b2 (row-0 corr), w2 = a3b1+a4b2 (col-0 corr)
        cw1[ee]  = pack2(r1[0] * (p1[0] * q1[0] + p2[0] * q2[0]),
                         r1[1] * (p1[1] * q1[1] + p2[1] * q2[1]));
        cw2[ee]  = pack2(r2[0] * (p3[0] * q1[0] + p4[0] * q2[0]),
                         r2[1] * (p3[1] * q1[1] + p4[1] * q2[1]));
    }

    // zero the private per-column states (no cross-thread sharing -> no syncs)
#pragma unroll
    for (int j = 0; j < LS; j++) {
        sh_z[j][tid] = make_ulonglong2(0ULL, 0ULL);
        sh_t[j][tid] = make_ulonglong2(0ULL, 0ULL);
    }

    const float* xp = x + b * NE + e0;
    __half* op = g_scrh[dir] + b * NE + e0;

    for (int ib = 0; ib < 8; ib++) {   // 8 blocks of 4 rows
        u64 p[4][2], xv[4][2], ss[4][2];
        float2 uprev[4];
#pragma unroll
        for (int r = 0; r < 4; r++) {
            p[r][0] = p[r][1] = xv[r][0] = xv[r][1] = ss[r][0] = ss[r][1] = 0ULL;
            uprev[r] = make_float2(0.f, 0.f);
        }
        int rowoff[4];
#pragma unroll
        for (int r = 0; r < 4; r++) {
            int i  = ib * 4 + r;
            int ip = fi ? (LS - 1 - i) : i;
            rowoff[r] = (ip * LS) * BE;
        }

        // prefetch column j=0
        float2 u_cur[4], u_nxt[4];
        {
            const int jB0 = (fj ? (LS - 1) : 0) * BE;
#pragma unroll
            for (int r = 0; r < 4; r++)
                u_cur[r] = *reinterpret_cast<const float2*>(xp + rowoff[r] + jB0);
        }

        for (int j = 0; j < LS; j++) {
            const int jp = fj ? (LS - 1 - j) : j;
            const int jB = jp * BE;

            // issue next column's loads before consuming this column
            if (j < LS - 1) {
                const int jBn = (fj ? (LS - 2 - j) : (j + 1)) * BE;
#pragma unroll
                for (int r = 0; r < 4; r++)
                    u_nxt[r] = *reinterpret_cast<const float2*>(xp + rowoff[r] + jBn);
            }

            ulonglong2 zz = sh_z[j][tid];
            ulonglong2 tt = sh_t[j][tid];
            u64 z[2] = { zz.x, zz.y };
            u64 t[2] = { tt.x, tt.y };

#pragma unroll
            for (int r = 0; r < 4; r++) {
                const float2 uv  = u_cur[r];
                const float2 upv = uprev[r];
                float y[2];
#pragma unroll
                for (int ee = 0; ee < 2; ee++) {
                    const float us  = ee ? uv.y  : uv.x;
                    const float ups = ee ? upv.y : upv.x;
                    const u64 u2  = pack2(us, us);
                    const u64 up2 = pack2(ups, ups);
                    // row-0 boundary correction (uses u[i,j-1])
                    u64 ns = fma2(a1e[ee], ss[r][ee], up2);
                    // vertical state
                    u64 nv = fma2(bb2e[ee], u2, z[ee]);
                    // scaled horizontal state p = a3*xh
                    u64 pn = fma2(a1e[ee], p[r][ee],
                                  fma2(a32[ee], xv[r][ee], mul2(a31[ee], u2)));
                    // vertical carry for next row
                    z[ee] = fma2(a4e[ee], nv, pn);
                    // y = c1p.p + cw1.ns + c2.nv + cw2.t
                    u64 acc = fma2(c1p[ee], pn,
                               fma2(cw1[ee], ns,
                                fma2(cw2[ee], t[ee], mul2(c2e[ee], nv))));
                    // col-0 boundary correction (uses u[i-1,j]; y used old t)
                    t[ee] = fma2(a4e[ee], t[ee], u2);
                    p[r][ee]  = pn;
                    xv[r][ee] = nv;
                    ss[r][ee] = ns;
                    float2 av = unpack2(acc);
                    y[ee] = av.x + av.y;
                }
                st_h2_cs(op + rowoff[r] + jB, __floats2half2_rn(y[0], y[1]));
                uprev[r] = uv;
            }
            sh_z[j][tid] = make_ulonglong2(z[0], z[1]);
            sh_t[j][tid] = make_ulonglong2(t[0], t[1]);

#pragma unroll
            for (int r = 0; r < 4; r++) u_cur[r] = u_nxt[r];
        }
    }
}

// ---------------------------------------------------------------------------
// Epilogue: out = silu( y0+y1+y2+y3 + x*omega ). 8 elems/thread.
// Scratch reads are streaming (read-once) fp16.
// ---------------------------------------------------------------------------
__global__ void __launch_bounds__(256) ssm_epilogue(
    const float* __restrict__ x,
    const float* __restrict__ omega,
    float* __restrict__ out)
{
    const int idx = (blockIdx.x * 256 + threadIdx.x) * 8;

    float acc[8];
#pragma unroll
    for (int k = 0; k < 8; k++) acc[k] = 0.f;

#pragma unroll
    for (int d = 0; d < 4; d++) {
        uint4 raw = __ldcs(reinterpret_cast<const uint4*>(&g_scrh[d][idx]));
        const unsigned* rw = reinterpret_cast<const unsigned*>(&raw);
#pragma unroll
        for (int p = 0; p < 4; p++) {
            __half2 hv = *reinterpret_cast<const __half2*>(&rw[p]);
            float2 fv = __half22float2(hv);
            acc[2 * p + 0] += fv.x;
            acc[2 * p + 1] += fv.y;
        }
    }

    float4 x0 = *reinterpret_cast<const float4*>(x + idx);
    float4 x1 = *reinterpret_cast<const float4*>(x + idx + 4);
    const int e = idx & (NE - 1);
    float4 o0 = *reinterpret_cast<const float4*>(omega + e);
    float4 o1 = *reinterpret_cast<const float4*>(omega + e + 4);

    float z[8];
    z[0] = acc[0] + x0.x * o0.x;
    z[1] = acc[1] + x0.y * o0.y;
    z[2] = acc[2] + x0.z * o0.z;
    z[3] = acc[3] + x0.w * o0.w;
    z[4] = acc[4] + x1.x * o1.x;
    z[5] = acc[5] + x1.y * o1.y;
    z[6] = acc[6] + x1.z * o1.z;
    z[7] = acc[7] + x1.w * o1.w;

    float4 r0, r1;
    r0.x = z[0] / (1.0f + expf(-z[0]));
    r0.y = z[1] / (1.0f + expf(-z[1]));
    r0.z = z[2] / (1.0f + expf(-z[2]));
    r0.w = z[3] / (1.0f + expf(-z[3]));
    r1.x = z[4] / (1.0f + expf(-z[4]));
    r1.y = z[5] / (1.0f + expf(-z[5]));
    r1.z = z[6] / (1.0f + expf(-z[6]));
    r1.w = z[7] / (1.0f + expf(-z[7]));
    *reinterpret_cast<float4*>(out + idx)     = r0;
    *reinterpret_cast<float4*>(out + idx + 4) = r1;
}

extern "C" void kernel_launch(void* const* d_in, const int* in_sizes, int n_in,
                              void* d_out, int out_size)
{
    const float* x   = (const float*)d_in[0];
    const float* A1v = (const float*)d_in[1];
    const float* A2v = (const float*)d_in[2];
    const float* A3v = (const float*)d_in[3];
    const float* A4v = (const float*)d_in[4];
    const float* B1v = (const float*)d_in[5];
    const float* B2v = (const float*)d_in[6];
    const float* C1v = (const float*)d_in[7];
    const float* C2v = (const float*)d_in[8];
    const float* om  = (const float*)d_in[9];
    float* out = (float*)d_out;

    // 4 dirs * 16 b * 512 e-pairs = 32768 threads; 1024 CTAs of 32 -> 1 wave
    ssm_scan<<<1024, 32>>>(x, A1v, A2v, A3v, A4v, B1v, B2v, C1v, C2v);
    ssm_epilogue<<<S_TOT / 8 / 256, 256>>>(x, om, out);
}

// round 5
// speedup vs baseline: 1.3374x; 1.3374x over previous
#include <cuda_runtime.h>
#include <cuda_fp16.h>
#include <math.h>

// Problem constants
#define LS       32
#define SB       1024            // S = LS*LS
#define NB       16              // batch
#define NE       1024            // embedding
#define BE       (NB*NE)         // 16384: stride between spatial positions
#define S_TOT    (SB*NB*NE)      // 16,777,216 elements

// fp16 scratch for all 4 direction outputs (128 MB)
__device__ __half g_scrh[4][S_TOT];

typedef unsigned long long u64;

__device__ __forceinline__ float sigm(float v) { return 1.0f / (1.0f + expf(-v)); }

// ---- packed f32x2 helpers (sm_103a paired-fp32 ops, PTX-only) ----
__device__ __forceinline__ u64 pack2(float lo, float hi) {
    u64 r; asm("mov.b64 %0, {%1,%2};" : "=l"(r) : "f"(lo), "f"(hi)); return r;
}
__device__ __forceinline__ float2 unpack2(u64 v) {
    float2 r; asm("mov.b64 {%0,%1}, %2;" : "=f"(r.x), "=f"(r.y) : "l"(v)); return r;
}
__device__ __forceinline__ u64 fma2(u64 a, u64 b, u64 c) {
    u64 d; asm("fma.rn.f32x2 %0,%1,%2,%3;" : "=l"(d) : "l"(a), "l"(b), "l"(c)); return d;
}
__device__ __forceinline__ u64 mul2(u64 a, u64 b) {
    u64 d; asm("mul.rn.f32x2 %0,%1,%2;" : "=l"(d) : "l"(a), "l"(b)); return d;
}

__device__ __forceinline__ void st_half_cs(__half* p, float v) {
    unsigned short h = __half_as_ushort(__float2half_rn(v));
    asm volatile("st.global.cs.u16 [%0], %1;" :: "l"(p), "h"(h) : "memory");
}

// noop used only to rotate the ncu sampling window onto the scan kernel
__global__ void noop_k() {}

// ---------------------------------------------------------------------------
// Scan kernel: one thread per (dir, b, e). 2D SSM recurrence (= causal 2D
// conv with the impulse response) on the direction-flipped image, plus the
// two 1D boundary-correction recurrences implementing the reference's
// K row-0/col-0 doubling. N=2 state pairs packed in f32x2.
//
// Reparametrized states (11 f32x2/pixel):
//   p   = a3*xh :  p' = a1*p + (a3a2)*xv + (a3b1)*u
//   nv  = z + b2*u            (z = smem vertical carry from row above)
//   z'  = p' + a4*nv
//   ns  : ns = a1*ns + u_prev (row-0 corr, w folded into cw1)
//   t   : y uses old t, then t = a4*t + u (col-0 corr, w2 folded into cw2)
//   y   = (c1/a3).p' + (c1w).ns + c2.nv + (c2w2).t
//
// 8-row register blocking; per-column states {z,t} = 16B/thread in SMEM
// (32KB/CTA of 64 thr -> 7 CTAs/SM = 14 warps/SM, 1024 CTAs = 1 wave).
// Column j+1 input loads prefetched while computing column j.
// ---------------------------------------------------------------------------
__global__ void __launch_bounds__(64, 7) ssm_scan(
    const float* __restrict__ x,
    const float* __restrict__ A1v, const float* __restrict__ A2v,
    const float* __restrict__ A3v, const float* __restrict__ A4v,
    const float* __restrict__ B1v, const float* __restrict__ B2v,
    const float* __restrict__ C1v, const float* __restrict__ C2v)
{
    __shared__ u64 sh_z[LS][64];
    __shared__ u64 sh_t[LS][64];

    const int tid = threadIdx.x;
    const int g   = blockIdx.x * 64 + tid;
    const int e   = g & (NE - 1);
    const int b   = (g >> 10) & (NB - 1);
    const int dir = g >> 14;                 // 0..3
    const int h   = (dir << 6) | (e & 63);   // kernel channel
    const bool fi = (dir & 1) != 0;          // flip rows (axis -2)
    const bool fj = (dir & 2) != 0;          // flip cols (axis -1)

    const float scale = 0.70710678118654752440f;  // sqrt(1/N), N=2

    float p1[2], p2[2], p3[2], p4[2], q1[2], q2[2], r1[2], r2[2];
#pragma unroll
    for (int n = 0; n < 2; n++) {
        p1[n] = sigm(A1v[2 * h + n]);
        p2[n] = sigm(A2v[2 * h + n]);
        p3[n] = sigm(A3v[2 * h + n]);
        p4[n] = sigm(A4v[2 * h + n]);
        q1[n] = sigm(B1v[2 * h + n]);
        q2[n] = sigm(B2v[2 * h + n]);
        r1[n] = scale * C1v[2 * h + n];
        r2[n] = scale * C2v[2 * h + n];
    }
    const u64 a1  = pack2(p1[0], p1[1]);
    const u64 a32 = pack2(p3[0] * p2[0], p3[1] * p2[1]);
    const u64 a31 = pack2(p3[0] * q1[0], p3[1] * q1[1]);
    const u64 bb2 = pack2(q2[0], q2[1]);
    const u64 a4  = pack2(p4[0], p4[1]);
    const u64 c1p = pack2(r1[0] / p3[0], r1[1] / p3[1]);
    const u64 c2  = pack2(r2[0], r2[1]);
    // w = a1b1+a2b2 (row-0 corr), w2 = a3b1+a4b2 (col-0 corr)
    const u64 cw1 = pack2(r1[0] * (p1[0] * q1[0] + p2[0] * q2[0]),
                          r1[1] * (p1[1] * q1[1] + p2[1] * q2[1]));
    const u64 cw2 = pack2(r2[0] * (p3[0] * q1[0] + p4[0] * q2[0]),
                          r2[1] * (p3[1] * q1[1] + p4[1] * q2[1]));

    // zero the private per-column states (no cross-thread sharing -> no syncs)
#pragma unroll
    for (int j = 0; j < LS; j++) {
        sh_z[j][tid] = 0ULL;
        sh_t[j][tid] = 0ULL;
    }

    const float* xp = x + b * NE + e;
    __half* op = g_scrh[dir] + b * NE + e;

    for (int ib = 0; ib < 4; ib++) {
        // per-row horizontal states for the 8 rows of this block
        u64 p[8], xv[8], ss[8], u2p[8];
#pragma unroll
        for (int r = 0; r < 8; r++) { p[r] = xv[r] = ss[r] = u2p[r] = 0ULL; }

        int rowoff[8];
#pragma unroll
        for (int r = 0; r < 8; r++) {
            int i  = ib * 8 + r;
            int ip = fi ? (LS - 1 - i) : i;
            rowoff[r] = (ip * LS) * BE;
        }

        // prefetch column j=0
        float u_cur[8], u_nxt[8];
        {
            const int jB0 = (fj ? (LS - 1) : 0) * BE;
#pragma unroll
            for (int r = 0; r < 8; r++) u_cur[r] = xp[rowoff[r] + jB0];
        }

        for (int j = 0; j < LS; j++) {
            const int jp = fj ? (LS - 1 - j) : j;
            const int jB = jp * BE;

            // issue next column's loads before consuming this column
            if (j < LS - 1) {
                const int jBn = (fj ? (LS - 2 - j) : (j + 1)) * BE;
#pragma unroll
                for (int r = 0; r < 8; r++) u_nxt[r] = xp[rowoff[r] + jBn];
            }

            u64 z = sh_z[j][tid];   // vertical carry from row above
            u64 t = sh_t[j][tid];   // col-0 correction state

#pragma unroll
            for (int r = 0; r < 8; r++) {
                const float us = u_cur[r];
                const u64 u2 = pack2(us, us);
                // row-0 boundary correction (uses u[i,j-1])
                u64 ns = fma2(a1, ss[r], u2p[r]);
                // vertical state
                u64 nv = fma2(bb2, u2, z);
                // scaled horizontal state p = a3*xh
                u64 pn = fma2(a1, p[r], fma2(a32, xv[r], mul2(a31, u2)));
                // vertical carry for next row
                z = fma2(a4, nv, pn);
                // y = c1p.p + cw1.ns + c2.nv + cw2.t   (t is pre-update)
                u64 acc = fma2(c1p, pn,
                           fma2(cw1, ns,
                            fma2(cw2, t, mul2(c2, nv))));
                // col-0 boundary correction (uses u[i-1,j])
                t = fma2(a4, t, u2);
                // roll states
                p[r]  = pn;
                xv[r] = nv;
                ss[r] = ns;
                u2p[r] = u2;
                float2 av = unpack2(acc);
                st_half_cs(op + rowoff[r] + jB, av.x + av.y);
            }
            sh_z[j][tid] = z;
            sh_t[j][tid] = t;

#pragma unroll
            for (int r = 0; r < 8; r++) u_cur[r] = u_nxt[r];
        }
    }
}

// ---------------------------------------------------------------------------
// Epilogue: out = silu( y0+y1+y2+y3 + x*omega ). 8 elems/thread.
// Scratch reads are streaming (read-once) fp16.
// ---------------------------------------------------------------------------
__global__ void __launch_bounds__(256) ssm_epilogue(
    const float* __restrict__ x,
    const float* __restrict__ omega,
    float* __restrict__ out)
{
    const int idx = (blockIdx.x * 256 + threadIdx.x) * 8;

    float acc[8];
#pragma unroll
    for (int k = 0; k < 8; k++) acc[k] = 0.f;

#pragma unroll
    for (int d = 0; d < 4; d++) {
        uint4 raw = __ldcs(reinterpret_cast<const uint4*>(&g_scrh[d][idx]));
        const unsigned* rw = reinterpret_cast<const unsigned*>(&raw);
#pragma unroll
        for (int p = 0; p < 4; p++) {
            __half2 hv = *reinterpret_cast<const __half2*>(&rw[p]);
            float2 fv = __half22float2(hv);
            acc[2 * p + 0] += fv.x;
            acc[2 * p + 1] += fv.y;
        }
    }

    float4 x0 = *reinterpret_cast<const float4*>(x + idx);
    float4 x1 = *reinterpret_cast<const float4*>(x + idx + 4);
    const int e = idx & (NE - 1);
    float4 o0 = *reinterpret_cast<const float4*>(omega + e);
    float4 o1 = *reinterpret_cast<const float4*>(omega + e + 4);

    float z[8];
    z[0] = acc[0] + x0.x * o0.x;
    z[1] = acc[1] + x0.y * o0.y;
    z[2] = acc[2] + x0.z * o0.z;
    z[3] = acc[3] + x0.w * o0.w;
    z[4] = acc[4] + x1.x * o1.x;
    z[5] = acc[5] + x1.y * o1.y;
    z[6] = acc[6] + x1.z * o1.z;
    z[7] = acc[7] + x1.w * o1.w;

    float4 r0, r1;
    r0.x = z[0] / (1.0f + expf(-z[0]));
    r0.y = z[1] / (1.0f + expf(-z[1]));
    r0.z = z[2] / (1.0f + expf(-z[2]));
    r0.w = z[3] / (1.0f + expf(-z[3]));
    r1.x = z[4] / (1.0f + expf(-z[4]));
    r1.y = z[5] / (1.0f + expf(-z[5]));
    r1.z = z[6] / (1.0f + expf(-z[6]));
    r1.w = z[7] / (1.0f + expf(-z[7]));
    *reinterpret_cast<float4*>(out + idx)     = r0;
    *reinterpret_cast<float4*>(out + idx + 4) = r1;
}

extern "C" void kernel_launch(void* const* d_in, const int* in_sizes, int n_in,
                              void* d_out, int out_size)
{
    const float* x   = (const float*)d_in[0];
    const float* A1v = (const float*)d_in[1];
    const float* A2v = (const float*)d_in[2];
    const float* A3v = (const float*)d_in[3];
    const float* A4v = (const float*)d_in[4];
    const float* B1v = (const float*)d_in[5];
    const float* B2v = (const float*)d_in[6];
    const float* C1v = (const float*)d_in[7];
    const float* C2v = (const float*)d_in[8];
    const float* om  = (const float*)d_in[9];
    float* out = (float*)d_out;

    // 4-launch cycle so ncu (-s 5 -c 1) lands on the SCAN (launch #6).
    noop_k<<<1, 32>>>();
    // 4 dirs * 16 b * 1024 e = 65536 threads; 1024 CTAs of 64 -> 1 wave
    ssm_scan<<<1024, 64>>>(x, A1v, A2v, A3v, A4v, B1v, B2v, C1v, C2v);
    ssm_epilogue<<<S_TOT / 8 / 256, 256>>>(x, om, out);
    noop_k<<<1, 32>>>();
}

// round 6
// speedup vs baseline: 1.3506x; 1.0099x over previous
#include <cuda_runtime.h>
#include <cuda_fp16.h>
#include <math.h>

// Problem constants
#define LS       32
#define SB       1024            // S = LS*LS
#define NB       16              // batch
#define NE       1024            // embedding
#define BE       (NB*NE)         // 16384: stride between spatial positions
#define S_TOT    (SB*NB*NE)      // 16,777,216 elements

// fp16 scratch, pair-interleaved layout (128 MB total):
//   half index = dir*S_TOT + ((i*16 + jpair)*BE + b*NE + e)*2 + parity
// parity 0 = physical column 2*jpair, parity 1 = 2*jpair+1.
__device__ __half g_scrh[4ULL * S_TOT];

typedef unsigned long long u64;

__device__ __forceinline__ float sigm(float v) { return 1.0f / (1.0f + expf(-v)); }

// ---- packed f32x2 helpers (sm_103a paired-fp32 ops, PTX-only) ----
__device__ __forceinline__ u64 pack2(float lo, float hi) {
    u64 r; asm("mov.b64 %0, {%1,%2};" : "=l"(r) : "f"(lo), "f"(hi)); return r;
}
__device__ __forceinline__ float2 unpack2(u64 v) {
    float2 r; asm("mov.b64 {%0,%1}, %2;" : "=f"(r.x), "=f"(r.y) : "l"(v)); return r;
}
__device__ __forceinline__ u64 fma2(u64 a, u64 b, u64 c) {
    u64 d; asm("fma.rn.f32x2 %0,%1,%2,%3;" : "=l"(d) : "l"(a), "l"(b), "l"(c)); return d;
}
__device__ __forceinline__ u64 mul2(u64 a, u64 b) {
    u64 d; asm("mul.rn.f32x2 %0,%1,%2;" : "=l"(d) : "l"(a), "l"(b)); return d;
}

__device__ __forceinline__ void st_h2_cs(__half* p, __half2 v) {
    unsigned raw = *reinterpret_cast<unsigned*>(&v);
    asm volatile("st.global.cs.u32 [%0], %1;" :: "l"(p), "r"(raw) : "memory");
}

// noop used only to rotate the ncu sampling window
__global__ void noop_k() {}

// ---------------------------------------------------------------------------
// Scan kernel: one thread per (dir, b, e). 2D SSM recurrence (= causal 2D
// conv with the impulse response) on the direction-flipped image, plus the
// two 1D boundary-correction recurrences implementing the reference's
// K row-0/col-0 doubling. N=2 state pairs packed in f32x2 (11 ops/pixel).
//
// Logical columns processed in PAIRS: one coalesced STG.32 (half2) per row
// per pair into the pair-interleaved scratch; the 16 input loads for the
// next pair are prefetched at pair start (covers ~2 column-steps of work).
// 8-row register blocking; per-column {z,t} carries in SMEM
// (32KB/CTA of 64 thr -> 7 CTAs/SM = 14 warps/SM, 1024 CTAs = 1 wave).
// ---------------------------------------------------------------------------
__global__ void __launch_bounds__(64, 7) ssm_scan(
    const float* __restrict__ x,
    const float* __restrict__ A1v, const float* __restrict__ A2v,
    const float* __restrict__ A3v, const float* __restrict__ A4v,
    const float* __restrict__ B1v, const float* __restrict__ B2v,
    const float* __restrict__ C1v, const float* __restrict__ C2v)
{
    __shared__ u64 sh_z[LS][64];
    __shared__ u64 sh_t[LS][64];

    const int tid = threadIdx.x;
    const int g   = blockIdx.x * 64 + tid;
    const int e   = g & (NE - 1);
    const int b   = (g >> 10) & (NB - 1);
    const int dir = g >> 14;                 // 0..3
    const int h   = (dir << 6) | (e & 63);   // kernel channel
    const bool fi = (dir & 1) != 0;          // flip rows (axis -2)
    const bool fj = (dir & 2) != 0;          // flip cols (axis -1)

    const float scale = 0.70710678118654752440f;  // sqrt(1/N), N=2

    float p1[2], p2[2], p3[2], p4[2], q1[2], q2[2], r1[2], r2[2];
#pragma unroll
    for (int n = 0; n < 2; n++) {
        p1[n] = sigm(A1v[2 * h + n]);
        p2[n] = sigm(A2v[2 * h + n]);
        p3[n] = sigm(A3v[2 * h + n]);
        p4[n] = sigm(A4v[2 * h + n]);
        q1[n] = sigm(B1v[2 * h + n]);
        q2[n] = sigm(B2v[2 * h + n]);
        r1[n] = scale * C1v[2 * h + n];
        r2[n] = scale * C2v[2 * h + n];
    }
    const u64 a1  = pack2(p1[0], p1[1]);
    const u64 a32 = pack2(p3[0] * p2[0], p3[1] * p2[1]);
    const u64 a31 = pack2(p3[0] * q1[0], p3[1] * q1[1]);
    const u64 bb2 = pack2(q2[0], q2[1]);
    const u64 a4  = pack2(p4[0], p4[1]);
    const u64 c1p = pack2(r1[0] / p3[0], r1[1] / p3[1]);
    const u64 c2  = pack2(r2[0], r2[1]);
    const u64 cw1 = pack2(r1[0] * (p1[0] * q1[0] + p2[0] * q2[0]),
                          r1[1] * (p1[1] * q1[1] + p2[1] * q2[1]));
    const u64 cw2 = pack2(r2[0] * (p3[0] * q1[0] + p4[0] * q2[0]),
                          r2[1] * (p3[1] * q1[1] + p4[1] * q2[1]));

    // zero the private per-column carries (no cross-thread sharing -> no syncs)
#pragma unroll
    for (int j = 0; j < LS; j++) {
        sh_z[j][tid] = 0ULL;
        sh_t[j][tid] = 0ULL;
    }

    const float* xp = x + b * NE + e;
    __half* op = g_scrh + (unsigned)dir * (unsigned)S_TOT + (b * NE + e) * 2;

    for (int ib = 0; ib < 4; ib++) {
        u64 p[8], xv[8], ss[8];
        float upf[8];
#pragma unroll
        for (int r = 0; r < 8; r++) { p[r] = xv[r] = ss[r] = 0ULL; upf[r] = 0.f; }

        int rowoff[8];   // float offset into x; numerically equal half offset into scratch
#pragma unroll
        for (int r = 0; r < 8; r++) {
            int i  = ib * 8 + r;
            int ip = fi ? (LS - 1 - i) : i;
            rowoff[r] = (ip * LS) * BE;
        }

        // preload pair 0 (logical columns 0,1)
        float u0[8], u1[8], n0[8], n1[8];
        {
            const int c0 = (fj ? (LS - 1) : 0) * BE;
            const int c1 = (fj ? (LS - 2) : 1) * BE;
#pragma unroll
            for (int r = 0; r < 8; r++) {
                u0[r] = xp[rowoff[r] + c0];
                u1[r] = xp[rowoff[r] + c1];
            }
        }

        for (int m = 0; m < 16; m++) {
            // prefetch next pair's 16 loads
            if (m < 15) {
                const int c0n = (fj ? (LS - 3 - 2 * m) : (2 * m + 2)) * BE;
                const int c1n = (fj ? (LS - 4 - 2 * m) : (2 * m + 3)) * BE;
#pragma unroll
                for (int r = 0; r < 8; r++) {
                    n0[r] = xp[rowoff[r] + c0n];
                    n1[r] = xp[rowoff[r] + c1n];
                }
            }

            const int jl = 2 * m;
            u64 z0 = sh_z[jl][tid],     t0 = sh_t[jl][tid];
            u64 z1 = sh_z[jl + 1][tid], t1 = sh_t[jl + 1][tid];

            const int jph = fj ? (15 - m) : m;       // physical pair index
            const int sOff = jph * 2 * BE;           // half offset of pair

#pragma unroll
            for (int r = 0; r < 8; r++) {
                // ---- logical column jl ----
                const float usa = u0[r];
                const u64 u2a = pack2(usa, usa);
                const u64 upa = pack2(upf[r], upf[r]);
                u64 ns = fma2(a1, ss[r], upa);
                u64 nv = fma2(bb2, u2a, z0);
                u64 pn = fma2(a1, p[r], fma2(a32, xv[r], mul2(a31, u2a)));
                z0 = fma2(a4, nv, pn);
                u64 acc = fma2(c1p, pn,
                           fma2(cw1, ns,
                            fma2(cw2, t0, mul2(c2, nv))));
                t0 = fma2(a4, t0, u2a);
                float2 ava = unpack2(acc);
                const float ye = ava.x + ava.y;

                // ---- logical column jl+1 (u_prev = u0) ----
                const float usb = u1[r];
                const u64 u2b = pack2(usb, usb);
                u64 ns2 = fma2(a1, ns, u2a);
                u64 nv2 = fma2(bb2, u2b, z1);
                u64 pn2 = fma2(a1, pn, fma2(a32, nv, mul2(a31, u2b)));
                z1 = fma2(a4, nv2, pn2);
                u64 acc2 = fma2(c1p, pn2,
                            fma2(cw1, ns2,
                             fma2(cw2, t1, mul2(c2, nv2))));
                t1 = fma2(a4, t1, u2b);
                float2 avb = unpack2(acc2);
                const float yo = avb.x + avb.y;

                // roll row states past the pair
                p[r]  = pn2;
                xv[r] = nv2;
                ss[r] = ns2;
                upf[r] = usb;

                // one coalesced half2 store per row per pair
                // parity0 = physical even col: ye if !fj (c0=2m), else yo (c1=30-2m)
                __half2 hv = fj ? __floats2half2_rn(yo, ye)
                                : __floats2half2_rn(ye, yo);
                st_h2_cs(op + rowoff[r] + sOff, hv);
            }
            sh_z[jl][tid] = z0;     sh_t[jl][tid] = t0;
            sh_z[jl + 1][tid] = z1; sh_t[jl + 1][tid] = t1;

#pragma unroll
            for (int r = 0; r < 8; r++) { u0[r] = n0[r]; u1[r] = n1[r]; }
        }
    }
}

// ---------------------------------------------------------------------------
// Epilogue: out = silu( y0+y1+y2+y3 + x*omega ). Each thread: 4 e's x 2
// physical columns (one scratch pair). Scratch reads streaming uint4.
// ---------------------------------------------------------------------------
__global__ void __launch_bounds__(256) ssm_epilogue(
    const float* __restrict__ x,
    const float* __restrict__ omega,
    float* __restrict__ out)
{
    const int t  = blockIdx.x * 256 + threadIdx.x;   // 0 .. S_TOT/8
    const int e0 = (t & 255) * 4;                    // 4-aligned e
    const int bi = (t >> 8) & 15;
    const int sp = t >> 12;                          // i*16 + jpair, [0,512)

    const unsigned hb = (unsigned)sp * (BE * 2) + (bi * NE + e0) * 2;

    float accE[4] = {0.f, 0.f, 0.f, 0.f};
    float accO[4] = {0.f, 0.f, 0.f, 0.f};
#pragma unroll
    for (int d = 0; d < 4; d++) {
        uint4 raw = __ldcs(reinterpret_cast<const uint4*>(
            g_scrh + (unsigned)d * (unsigned)S_TOT + hb));
        const unsigned* rw = reinterpret_cast<const unsigned*>(&raw);
#pragma unroll
        for (int k = 0; k < 4; k++) {
            __half2 hv = *reinterpret_cast<const __half2*>(&rw[k]);
            float2 fv = __half22float2(hv);
            accE[k] += fv.x;   // physical col 2*jpair
            accO[k] += fv.y;   // physical col 2*jpair+1
        }
    }

    const int s0 = sp * 2 * BE + bi * NE + e0;   // (i*32 + 2*jpair)*BE + ...
    const int s1 = s0 + BE;

    float4 x0 = *reinterpret_cast<const float4*>(x + s0);
    float4 x1 = *reinterpret_cast<const float4*>(x + s1);
    float4 om = *reinterpret_cast<const float4*>(omega + e0);

    float zE[4], zO[4];
    zE[0] = accE[0] + x0.x * om.x;  zO[0] = accO[0] + x1.x * om.x;
    zE[1] = accE[1] + x0.y * om.y;  zO[1] = accO[1] + x1.y * om.y;
    zE[2] = accE[2] + x0.z * om.z;  zO[2] = accO[2] + x1.z * om.z;
    zE[3] = accE[3] + x0.w * om.w;  zO[3] = accO[3] + x1.w * om.w;

    float4 r0, r1;
    r0.x = zE[0] / (1.0f + expf(-zE[0]));
    r0.y = zE[1] / (1.0f + expf(-zE[1]));
    r0.z = zE[2] / (1.0f + expf(-zE[2]));
    r0.w = zE[3] / (1.0f + expf(-zE[3]));
    r1.x = zO[0] / (1.0f + expf(-zO[0]));
    r1.y = zO[1] / (1.0f + expf(-zO[1]));
    r1.z = zO[2] / (1.0f + expf(-zO[2]));
    r1.w = zO[3] / (1.0f + expf(-zO[3]));
    *reinterpret_cast<float4*>(out + s0) = r0;
    *reinterpret_cast<float4*>(out + s1) = r1;
}

extern "C" void kernel_launch(void* const* d_in, const int* in_sizes, int n_in,
                              void* d_out, int out_size)
{
    const float* x   = (const float*)d_in[0];
    const float* A1v = (const float*)d_in[1];
    const float* A2v = (const float*)d_in[2];
    const float* A3v = (const float*)d_in[3];
    const float* A4v = (const float*)d_in[4];
    const float* B1v = (const float*)d_in[5];
    const float* B2v = (const float*)d_in[6];
    const float* C1v = (const float*)d_in[7];
    const float* C2v = (const float*)d_in[8];
    const float* om  = (const float*)d_in[9];
    float* out = (float*)d_out;

    // 4-launch cycle: under 'no-offset' ncu numbering #6 = epilogue (known),
    // under the '+1 offset' numbering #6 = SCAN (what we want to see).
    ssm_scan<<<1024, 64>>>(x, A1v, A2v, A3v, A4v, B1v, B2v, C1v, C2v);
    ssm_epilogue<<<S_TOT / 8 / 256, 256>>>(x, om, out);
    noop_k<<<1, 32>>>();
    noop_k<<<1, 32>>>();
}

// round 7
// speedup vs baseline: 1.6319x; 1.2083x over previous
#include <cuda_runtime.h>
#include <cuda_fp16.h>
#include <math.h>

// Problem constants
#define LS       32
#define SB       1024            // S = LS*LS
#define NB       16              // batch
#define NE       1024            // embedding
#define BE       (NB*NE)         // 16384: stride between spatial positions
#define S_TOT    (SB*NB*NE)      // 16,777,216 elements

// fp16 scratch, pair-interleaved layout (128 MB total):
//   half index = dir*S_TOT + ((i*16 + jpair)*BE + b*NE + e)*2 + parity
// parity 0 = physical column 2*jpair, parity 1 = 2*jpair+1.
__device__ __half g_scrh[4ULL * S_TOT];

typedef unsigned long long u64;

__device__ __forceinline__ float sigm(float v) { return 1.0f / (1.0f + expf(-v)); }

// ---- packed f32x2 helpers (sm_103a paired-fp32 ops, PTX-only) ----
__device__ __forceinline__ u64 pack2(float lo, float hi) {
    u64 r; asm("mov.b64 %0, {%1,%2};" : "=l"(r) : "f"(lo), "f"(hi)); return r;
}
__device__ __forceinline__ float2 unpack2(u64 v) {
    float2 r; asm("mov.b64 {%0,%1}, %2;" : "=f"(r.x), "=f"(r.y) : "l"(v)); return r;
}
__device__ __forceinline__ u64 fma2(u64 a, u64 b, u64 c) {
    u64 d; asm("fma.rn.f32x2 %0,%1,%2,%3;" : "=l"(d) : "l"(a), "l"(b), "l"(c)); return d;
}
__device__ __forceinline__ u64 mul2(u64 a, u64 b) {
    u64 d; asm("mul.rn.f32x2 %0,%1,%2;" : "=l"(d) : "l"(a), "l"(b)); return d;
}

__device__ __forceinline__ void st_h2_cs(__half* p, __half2 v) {
    unsigned raw = *reinterpret_cast<unsigned*>(&v);
    asm volatile("st.global.cs.u32 [%0], %1;" :: "l"(p), "r"(raw) : "memory");
}

// ---------------------------------------------------------------------------
// Scan kernel: one thread per (dir, b, e). 2D SSM recurrence (= causal 2D
// conv with the impulse response) on the direction-flipped image, plus the
// two 1D boundary-correction recurrences implementing the reference's
// K row-0/col-0 doubling. N=2 state pairs packed in f32x2 (11 ops/pixel).
//
// 128-thread CTAs so the 4 warps cover all 4 SMSPs (wid%4 mapping!).
// 4-row register blocking; per-column carries in SMEM: z as f32x2 (8B),
// col-0 state t as half2 (4B, requantized once per 4-row block) ->
// 12B/thread-col -> 48KB static SMEM -> 4 CTAs/SM, 512 CTAs = 1 wave,
// 16 warps/SM = 4 per SMSP.
// Columns processed in pairs: one coalesced STG.32 (half2) per row per
// pair into pair-interleaved scratch; next pair's 8 loads prefetched.
// ---------------------------------------------------------------------------
__global__ void __launch_bounds__(128, 4) ssm_scan(
    const float* __restrict__ x,
    const float* __restrict__ A1v, const float* __restrict__ A2v,
    const float* __restrict__ A3v, const float* __restrict__ A4v,
    const float* __restrict__ B1v, const float* __restrict__ B2v,
    const float* __restrict__ C1v, const float* __restrict__ C2v)
{
    __shared__ u64     sh_z[LS][128];   // 32 KB: vertical carry, f32x2
    __shared__ __half2 sh_t[LS][128];   // 16 KB: col-0 correction, half2

    const int tid = threadIdx.x;
    const int g   = blockIdx.x * 128 + tid;
    const int e   = g & (NE - 1);
    const int b   = (g >> 10) & (NB - 1);
    const int dir = g >> 14;                 // 0..3
    const int h   = (dir << 6) | (e & 63);   // kernel channel
    const bool fi = (dir & 1) != 0;          // flip rows (axis -2)
    const bool fj = (dir & 2) != 0;          // flip cols (axis -1)

    const float scale = 0.70710678118654752440f;  // sqrt(1/N), N=2

    float p1[2], p2[2], p3[2], p4[2], q1[2], q2[2], r1[2], r2[2];
#pragma unroll
    for (int n = 0; n < 2; n++) {
        p1[n] = sigm(A1v[2 * h + n]);
        p2[n] = sigm(A2v[2 * h + n]);
        p3[n] = sigm(A3v[2 * h + n]);
        p4[n] = sigm(A4v[2 * h + n]);
        q1[n] = sigm(B1v[2 * h + n]);
        q2[n] = sigm(B2v[2 * h + n]);
        r1[n] = scale * C1v[2 * h + n];
        r2[n] = scale * C2v[2 * h + n];
    }
    const u64 a1  = pack2(p1[0], p1[1]);
    const u64 a32 = pack2(p3[0] * p2[0], p3[1] * p2[1]);
    const u64 a31 = pack2(p3[0] * q1[0], p3[1] * q1[1]);
    const u64 bb2 = pack2(q2[0], q2[1]);
    const u64 a4  = pack2(p4[0], p4[1]);
    const u64 c1p = pack2(r1[0] / p3[0], r1[1] / p3[1]);
    const u64 c2  = pack2(r2[0], r2[1]);
    const u64 cw1 = pack2(r1[0] * (p1[0] * q1[0] + p2[0] * q2[0]),
                          r1[1] * (p1[1] * q1[1] + p2[1] * q2[1]));
    const u64 cw2 = pack2(r2[0] * (p3[0] * q1[0] + p4[0] * q2[0]),
                          r2[1] * (p3[1] * q1[1] + p4[1] * q2[1]));

    // zero the private per-column carries (no cross-thread sharing -> no syncs)
#pragma unroll
    for (int j = 0; j < LS; j++) {
        sh_z[j][tid] = 0ULL;
        sh_t[j][tid] = __floats2half2_rn(0.f, 0.f);
    }

    const float* xp = x + b * NE + e;
    __half* op = g_scrh + (unsigned)dir * (unsigned)S_TOT + (b * NE + e) * 2;

    for (int ib = 0; ib < 8; ib++) {   // 8 blocks of 4 rows
        u64 p[4], xv[4], ss[4];
        float upf[4];
#pragma unroll
        for (int r = 0; r < 4; r++) { p[r] = xv[r] = ss[r] = 0ULL; upf[r] = 0.f; }

        int rowoff[4];   // float offset into x; numerically equal half offset into scratch
#pragma unroll
        for (int r = 0; r < 4; r++) {
            int i  = ib * 4 + r;
            int ip = fi ? (LS - 1 - i) : i;
            rowoff[r] = (ip * LS) * BE;
        }

        // preload pair 0 (logical columns 0,1)
        float u0[4], u1[4], n0[4], n1[4];
        {
            const int c0 = (fj ? (LS - 1) : 0) * BE;
            const int c1 = (fj ? (LS - 2) : 1) * BE;
#pragma unroll
            for (int r = 0; r < 4; r++) {
                u0[r] = xp[rowoff[r] + c0];
                u1[r] = xp[rowoff[r] + c1];
            }
        }

        for (int m = 0; m < 16; m++) {
            // prefetch next pair's 8 loads
            if (m < 15) {
                const int c0n = (fj ? (LS - 3 - 2 * m) : (2 * m + 2)) * BE;
                const int c1n = (fj ? (LS - 4 - 2 * m) : (2 * m + 3)) * BE;
#pragma unroll
                for (int r = 0; r < 4; r++) {
                    n0[r] = xp[rowoff[r] + c0n];
                    n1[r] = xp[rowoff[r] + c1n];
                }
            }

            const int jl = 2 * m;
            u64 z0 = sh_z[jl][tid];
            u64 z1 = sh_z[jl + 1][tid];
            u64 t0, t1;
            {
                float2 tf0 = __half22float2(sh_t[jl][tid]);
                float2 tf1 = __half22float2(sh_t[jl + 1][tid]);
                t0 = pack2(tf0.x, tf0.y);
                t1 = pack2(tf1.x, tf1.y);
            }

            const int jph = fj ? (15 - m) : m;       // physical pair index
            const int sOff = jph * 2 * BE;           // half offset of pair

#pragma unroll
            for (int r = 0; r < 4; r++) {
                // ---- logical column jl ----
                const float usa = u0[r];
                const u64 u2a = pack2(usa, usa);
                const u64 upa = pack2(upf[r], upf[r]);
                u64 ns = fma2(a1, ss[r], upa);
                u64 nv = fma2(bb2, u2a, z0);
                u64 pn = fma2(a1, p[r], fma2(a32, xv[r], mul2(a31, u2a)));
                z0 = fma2(a4, nv, pn);
                u64 acc = fma2(c1p, pn,
                           fma2(cw1, ns,
                            fma2(cw2, t0, mul2(c2, nv))));
                t0 = fma2(a4, t0, u2a);
                float2 ava = unpack2(acc);
                const float ye = ava.x + ava.y;

                // ---- logical column jl+1 (u_prev = u0) ----
                const float usb = u1[r];
                const u64 u2b = pack2(usb, usb);
                u64 ns2 = fma2(a1, ns, u2a);
                u64 nv2 = fma2(bb2, u2b, z1);
                u64 pn2 = fma2(a1, pn, fma2(a32, nv, mul2(a31, u2b)));
                z1 = fma2(a4, nv2, pn2);
                u64 acc2 = fma2(c1p, pn2,
                            fma2(cw1, ns2,
                             fma2(cw2, t1, mul2(c2, nv2))));
                t1 = fma2(a4, t1, u2b);
                float2 avb = unpack2(acc2);
                const float yo = avb.x + avb.y;

                // roll row states past the pair
                p[r]  = pn2;
                xv[r] = nv2;
                ss[r] = ns2;
                upf[r] = usb;

                // one coalesced half2 store per row per pair
                // parity0 = physical even col: ye if !fj (c0=2m), else yo
                __half2 hv = fj ? __floats2half2_rn(yo, ye)
                                : __floats2half2_rn(ye, yo);
                st_h2_cs(op + rowoff[r] + sOff, hv);
            }
            sh_z[jl][tid] = z0;
            sh_z[jl + 1][tid] = z1;
            {
                float2 tf0 = unpack2(t0);
                float2 tf1 = unpack2(t1);
                sh_t[jl][tid]     = __floats2half2_rn(tf0.x, tf0.y);
                sh_t[jl + 1][tid] = __floats2half2_rn(tf1.x, tf1.y);
            }

#pragma unroll
            for (int r = 0; r < 4; r++) { u0[r] = n0[r]; u1[r] = n1[r]; }
        }
    }
}

// ---------------------------------------------------------------------------
// Epilogue: out = silu( y0+y1+y2+y3 + x*omega ). Each thread: 4 e's x 2
// physical columns (one scratch pair). Scratch reads streaming uint4.
// ---------------------------------------------------------------------------
__global__ void __launch_bounds__(256) ssm_epilogue(
    const float* __restrict__ x,
    const float* __restrict__ omega,
    float* __restrict__ out)
{
    const int t  = blockIdx.x * 256 + threadIdx.x;   // 0 .. S_TOT/8
    const int e0 = (t & 255) * 4;                    // 4-aligned e
    const int bi = (t >> 8) & 15;
    const int sp = t >> 12;                          // i*16 + jpair, [0,512)

    const unsigned hb = (unsigned)sp * (BE * 2) + (bi * NE + e0) * 2;

    float accE[4] = {0.f, 0.f, 0.f, 0.f};
    float accO[4] = {0.f, 0.f, 0.f, 0.f};
#pragma unroll
    for (int d = 0; d < 4; d++) {
        uint4 raw = __ldcs(reinterpret_cast<const uint4*>(
            g_scrh + (unsigned)d * (unsigned)S_TOT + hb));
        const unsigned* rw = reinterpret_cast<const unsigned*>(&raw);
#pragma unroll
        for (int k = 0; k < 4; k++) {
            __half2 hv = *reinterpret_cast<const __half2*>(&rw[k]);
            float2 fv = __half22float2(hv);
            accE[k] += fv.x;   // physical col 2*jpair
            accO[k] += fv.y;   // physical col 2*jpair+1
        }
    }

    const int s0 = sp * 2 * BE + bi * NE + e0;   // (i*32 + 2*jpair)*BE + ...
    const int s1 = s0 + BE;

    float4 x0 = *reinterpret_cast<const float4*>(x + s0);
    float4 x1 = *reinterpret_cast<const float4*>(x + s1);
    float4 om = *reinterpret_cast<const float4*>(omega + e0);

    float zE[4], zO[4];
    zE[0] = accE[0] + x0.x * om.x;  zO[0] = accO[0] + x1.x * om.x;
    zE[1] = accE[1] + x0.y * om.y;  zO[1] = accO[1] + x1.y * om.y;
    zE[2] = accE[2] + x0.z * om.z;  zO[2] = accO[2] + x1.z * om.z;
    zE[3] = accE[3] + x0.w * om.w;  zO[3] = accO[3] + x1.w * om.w;

    float4 r0, r1;
    r0.x = zE[0] / (1.0f + expf(-zE[0]));
    r0.y = zE[1] / (1.0f + expf(-zE[1]));
    r0.z = zE[2] / (1.0f + expf(-zE[2]));
    r0.w = zE[3] / (1.0f + expf(-zE[3]));
    r1.x = zO[0] / (1.0f + expf(-zO[0]));
    r1.y = zO[1] / (1.0f + expf(-zO[1]));
    r1.z = zO[2] / (1.0f + expf(-zO[2]));
    r1.w = zO[3] / (1.0f + expf(-zO[3]));
    *reinterpret_cast<float4*>(out + s0) = r0;
    *reinterpret_cast<float4*>(out + s1) = r1;
}

extern "C" void kernel_launch(void* const* d_in, const int* in_sizes, int n_in,
                              void* d_out, int out_size)
{
    const float* x   = (const float*)d_in[0];
    const float* A1v = (const float*)d_in[1];
    const float* A2v = (const float*)d_in[2];
    const float* A3v = (const float*)d_in[3];
    const float* A4v = (const float*)d_in[4];
    const float* B1v = (const float*)d_in[5];
    const float* B2v = (const float*)d_in[6];
    const float* C1v = (const float*)d_in[7];
    const float* C2v = (const float*)d_in[8];
    const float* om  = (const float*)d_in[9];
    float* out = (float*)d_out;

    // 4 dirs * 16 b * 1024 e = 65536 threads; 512 CTAs of 128 -> 1 wave,
    // 4 warps/CTA so all 4 SMSPs are used.
    ssm_scan<<<512, 128>>>(x, A1v, A2v, A3v, A4v, B1v, B2v, C1v, C2v);
    ssm_epilogue<<<S_TOT / 8 / 256, 256>>>(x, om, out);
}